// round 11
// baseline (speedup 1.0000x reference)
#include <cuda_runtime.h>
#include <cuda_bf16.h>
#include <math.h>
#include <stdint.h>

#define BATCH  64
#define HD     128
#define OUTC   10

#define PITCHV 136      // V row pitch, bf16 elems
#define V0_OFF 0
#define V1_OFF (16 * PITCHV * 2)            // 4352
#define XS_OFF (2 * 16 * PITCHV * 2)        // 8704
#define LG_OFF (XS_OFF + 16 * 256 * 4)      // 25088
#define RI_OFF (LG_OFF + 64)
#define LT_OFF (RI_OFF + 64)
#define SMEM_MAIN (LT_OFF + 64)

// Chain matrices permuted into mma.m16n8k16 B-fragment order (bf16, 16.7 MB):
// uint32 index: (((m*8 + wc)*4 + nt)*4 + kp)*128 + lane*4 + j      [16384 u32 per m]
//   kc = 2*kp + (j>>1); reg = j&1
//   packed pair = M[k0][n], M[k0+1][n]; k0 = kc*16 + 2*(lane&3) + reg*8
//   n = wc*32 + nt*8 + (lane>>2);  M[k][2h+d] = cores[m][k][d][h]
__device__ uint32_t g_perm[(size_t)255 * 16384];

// ---------------- helpers ----------------
__device__ __forceinline__ uint32_t smem_u32(const void* p) {
    uint32_t a;
    asm("{ .reg .u64 t; cvta.to.shared.u64 t, %1; cvt.u32.u64 %0, t; }" : "=r"(a) : "l"(p));
    return a;
}
__device__ __forceinline__ uint32_t mapa_peer(uint32_t addr, uint32_t rank) {
    uint32_t r;
    asm("mapa.shared::cluster.u32 %0, %1, %2;" : "=r"(r) : "r"(addr), "r"(rank));
    return r;
}
__device__ __forceinline__ void st_cluster_u16(uint32_t addr, unsigned short v) {
    asm volatile("st.shared::cluster.u16 [%0], %1;" :: "r"(addr), "h"(v) : "memory");
}
#define CLUSTER_ARRIVE() asm volatile("barrier.cluster.arrive.aligned;" ::: "memory")
#define CLUSTER_WAIT()   asm volatile("barrier.cluster.wait.aligned;"   ::: "memory")

__device__ __forceinline__ void ldm_x4(uint32_t* r, uint32_t addr) {
    asm volatile("ldmatrix.sync.aligned.m8n8.x4.shared.b16 {%0,%1,%2,%3}, [%4];"
                 : "=r"(r[0]), "=r"(r[1]), "=r"(r[2]), "=r"(r[3]) : "r"(addr));
}
__device__ __forceinline__ void mma16816(float* c, const uint32_t* a,
                                         uint32_t b0, uint32_t b1) {
    asm volatile(
        "mma.sync.aligned.m16n8k16.row.col.f32.bf16.bf16.f32 "
        "{%0,%1,%2,%3}, {%4,%5,%6,%7}, {%8,%9}, {%0,%1,%2,%3};"
        : "+f"(c[0]), "+f"(c[1]), "+f"(c[2]), "+f"(c[3])
        : "r"(a[0]), "r"(a[1]), "r"(a[2]), "r"(a[3]), "r"(b0), "r"(b1));
}
__device__ __forceinline__ uint32_t packbf2(float a, float b) {
    __nv_bfloat162 t = __floats2bfloat162_rn(a, b);
    return *reinterpret_cast<uint32_t*>(&t);
}

// ---------------- pre-pass: cores fp32 -> fragment-permuted bf16 ----------------
__global__ void __launch_bounds__(256) conv_perm(const float* __restrict__ cores)
{
    size_t gid = (size_t)blockIdx.x * 256 + threadIdx.x;   // 255*16384 total
    int u = (int)(gid & 16383);
    int m = (int)(gid >> 14);
    int j    = u & 3;
    int lane = (u >> 2) & 31;
    int kp   = (u >> 7) & 3;
    int nt   = (u >> 9) & 3;
    int wc   = (u >> 11) & 7;
    int kc = 2 * kp + (j >> 1);
    int k0 = kc * 16 + 2 * (lane & 3) + ((j & 1) << 3);
    int n  = wc * 32 + nt * 8 + (lane >> 2);
    int h = n >> 1, d = n & 1;
    const float* base = cores + (size_t)m * 32768;
    float lo = base[((size_t)k0 * 2 + d) * 128 + h];
    float hi = base[((size_t)(k0 + 1) * 2 + d) * 128 + h];
    g_perm[gid] = packbf2(lo, hi);
}

// ---------------- renorm (128 threads, full 16x128 V buffer) ----------------
__device__ __forceinline__ void renorm128(char* vb, char* sm, bool final_,
                                          float* LOGS, float* RINV, float* LTOT)
{
    const int tid = threadIdx.x;
    int bb = tid >> 3, seg = tid & 7;
    __nv_bfloat16* vr = (__nv_bfloat16*)(vb + bb * (PITCHV * 2));
    float s = 0.f;
    #pragma unroll
    for (int j = 0; j < 16; ++j) {
        float f = __bfloat162float(vr[seg * 16 + j]);
        s = fmaf(f, f, s);
    }
    #pragma unroll
    for (int o = 4; o > 0; o >>= 1) s += __shfl_xor_sync(0xffffffffu, s, o);
    if (seg == 0) {
        float nrm = fmaxf(sqrtf(s), 1e-30f);
        if (final_) {
            RINV[bb] = 1.f / nrm;
            LTOT[bb] = LOGS[bb] + logf(nrm);
        } else {
            LOGS[bb] += logf(nrm);
            RINV[bb] = 1.f / nrm;
        }
    }
    __syncthreads();
    if (!final_) {
        float ri = RINV[bb];
        #pragma unroll
        for (int j = 0; j < 16; ++j)
            vr[seg * 16 + j] = __float2bfloat16(__bfloat162float(vr[seg * 16 + j]) * ri);
        __syncthreads();
    }
}

// ---------------- one chain step (cluster n-split) ----------------
__device__ __forceinline__ void step(
    int m, uint4* __restrict__ Bcur, uint4* __restrict__ Bnext, bool pre,
    char* sm, uint32_t smb, uint32_t peer_smb, uint32_t fragbase,
    int wcg, int l15, int lhi, int r, int q,
    float* XS, float* LOGS, float* RINV, float* LTOT)
{
    CLUSTER_WAIT();   // exchange e=m complete: full V(m) in local Vbuf[m&1]

    if (m > 0 && (m & 15) == 0)
        renorm128(sm + ((m & 1) ? V1_OFF : V0_OFF), sm, false, LOGS, RINV, LTOT);

    const uint32_t vro = smb + ((m & 1) ? V1_OFF : V0_OFF);
    const int      vwo = (m & 1) ? V0_OFF : V1_OFF;

    uint32_t A[8][4];
    #pragma unroll
    for (int kc = 0; kc < 8; ++kc)
        ldm_x4(A[kc], vro + (uint32_t)(l15 * PITCHV + kc * 16 + lhi) * 2);

    float acc[4][4];
    #pragma unroll
    for (int i = 0; i < 4; ++i)
        #pragma unroll
        for (int j = 0; j < 4; ++j) acc[i][j] = 0.f;

    #pragma unroll
    for (int kc = 0; kc < 8; ++kc)
        #pragma unroll
        for (int nt = 0; nt < 4; ++nt) {
            const uint4& v = Bcur[nt * 4 + (kc >> 1)];
            uint32_t b0 = (kc & 1) ? v.z : v.x;
            uint32_t b1 = (kc & 1) ? v.w : v.y;
            mma16816(acc[nt], A[kc], b0, b1);
        }

    // epilogue: combine (1-x)*U + x*W ; write local + peer halves
    const float xa = XS[r * 256 + m + 1];
    const float xb = XS[(r + 8) * 256 + m + 1];
    #pragma unroll
    for (int nt = 0; nt < 4; ++nt) {
        int h = wcg * 16 + nt * 4 + q;
        float v0 = fmaf(xa, acc[nt][1], (1.f - xa) * acc[nt][0]);
        float v1 = fmaf(xb, acc[nt][3], (1.f - xb) * acc[nt][2]);
        unsigned short h0 = __bfloat16_as_ushort(__float2bfloat16(v0));
        unsigned short h1 = __bfloat16_as_ushort(__float2bfloat16(v1));
        uint32_t off0 = (uint32_t)(vwo + r * (PITCHV * 2) + h * 2);
        uint32_t off1 = (uint32_t)(vwo + (r + 8) * (PITCHV * 2) + h * 2);
        *(unsigned short*)(sm + off0) = h0;
        *(unsigned short*)(sm + off1) = h1;
        st_cluster_u16(peer_smb + off0, h0);
        st_cluster_u16(peer_smb + off1, h1);
    }

    CLUSTER_ARRIVE();   // release: orders each thread's local+remote stores

    if (pre) {          // prefetch B(m+1) in the arrive->wait gap
        const uint4* bp = (const uint4*)g_perm + ((size_t)(m + 1) << 12) + fragbase;
        #pragma unroll
        for (int i = 0; i < 16; ++i) Bnext[i] = bp[i * 32];
    }
}

// ---------------- main: 2-CTA cluster, 4 warps/CTA, n-split ----------------
__global__ void __launch_bounds__(128, 1) __cluster_dims__(2, 1, 1) mps_chain(
    const float* __restrict__ x, const float* __restrict__ core0,
    const float* __restrict__ classifier, float* __restrict__ out)
{
    __shared__ char sm[SMEM_MAIN];
    uint32_t smb = smem_u32(sm);
    const int tid = threadIdx.x, lane = tid & 31, w = tid >> 5;
    const int rank = blockIdx.x & 1;
    const int b0 = (blockIdx.x >> 1) * 16;
    const int wcg = rank * 4 + w;                 // global 32-col slice 0..7
    const uint32_t peer_smb = mapa_peer(smb, rank ^ 1);

    float* XS   = (float*)(sm + XS_OFF);
    float* LOGS = (float*)(sm + LG_OFF);
    float* RINV = (float*)(sm + RI_OFF);
    float* LTOT = (float*)(sm + LT_OFF);

    const int l15 = lane & 15, lhi = (lane >> 4) << 3;
    const int r = lane >> 2, q = lane & 3;
    const uint32_t fragbase = (uint32_t)(wcg * 16) * 32 + lane;

    // preload B(0) early (independent of everything)
    uint4 B0[16], B1[16];
    {
        const uint4* bp = (const uint4*)g_perm + fragbase;
        #pragma unroll
        for (int i = 0; i < 16; ++i) B0[i] = bp[i * 32];
    }

    #pragma unroll
    for (int it = 0; it < 32; ++it) {
        int idx = it * 128 + tid;
        XS[idx] = x[(size_t)(b0 + (idx >> 8)) * 256 + (idx & 255)];
    }
    if (tid < 16) LOGS[tid] = 0.f;
    __syncthreads();

    // init full V0 locally (both CTAs identically)
    #pragma unroll
    for (int it = 0; it < 16; ++it) {
        int idx = it * 128 + tid;
        int bb = idx >> 7, h = idx & 127;
        float xv = XS[bb * 256];
        float v = (1.f - xv) * core0[h] + xv * core0[HD + h];
        *(__nv_bfloat16*)(sm + V0_OFF + bb * (PITCHV * 2) + h * 2) = __float2bfloat16(v);
    }
    __syncthreads();
    CLUSTER_ARRIVE();   // pairs with step 0's wait

    for (int mm = 0; mm < 127; ++mm) {
        step(2 * mm,     B0, B1, true, sm, smb, peer_smb, fragbase,
             wcg, l15, lhi, r, q, XS, LOGS, RINV, LTOT);
        step(2 * mm + 1, B1, B0, true, sm, smb, peer_smb, fragbase,
             wcg, l15, lhi, r, q, XS, LOGS, RINV, LTOT);
    }
    step(254, B0, B1, false, sm, smb, peer_smb, fragbase,
         wcg, l15, lhi, r, q, XS, LOGS, RINV, LTOT);

    CLUSTER_WAIT();     // final exchange: full V(255) in Vbuf[1]

    renorm128(sm + V1_OFF, sm, true, LOGS, RINV, LTOT);

    if (rank == 0) {
        for (int idx = tid; idx < 16 * OUTC; idx += 128) {
            int bb = idx / OUTC, o = idx % OUTC;
            const __nv_bfloat16* vr = (const __nv_bfloat16*)(sm + V1_OFF + bb * (PITCHV * 2));
            float s = 0.f;
            #pragma unroll
            for (int h = 0; h < HD; ++h)
                s = fmaf(__bfloat162float(vr[h]), classifier[o * HD + h], s);
            out[(size_t)(b0 + bb) * OUTC + o] = s * RINV[bb] + LTOT[bb];
        }
    }
    CLUSTER_ARRIVE();   // don't let rank1 exit while rank0 reads shared state
    CLUSTER_WAIT();
}

extern "C" void kernel_launch(void* const* d_in, const int* in_sizes, int n_in,
                              void* d_out, int out_size)
{
    (void)in_sizes; (void)n_in; (void)out_size;
    const float* x          = (const float*)d_in[0];
    const float* core0      = (const float*)d_in[1];
    const float* cores      = (const float*)d_in[2];
    const float* classifier = (const float*)d_in[3];
    float*       out        = (float*)d_out;

    conv_perm<<<16320, 256>>>(cores);      // 255*16384 threads
    mps_chain<<<8, 128>>>(x, core0, classifier, out);   // 4 clusters x 2 CTAs
}